// round 9
// baseline (speedup 1.0000x reference)
#include <cuda_runtime.h>
#include <stdint.h>

#define NLEV      5
#define NCLS      80
#define M_TOTAL   4900
#define CAND_CAP  4096
#define NBINS     2048
#define IMG_F     1280.0f
#define CONF_T    0.05f
#define NMS_T     0.6f
#define STG_CAP   2048
#define FULLMASK  0xFFFFFFFFu

__constant__ int d_LN[NLEV]   = {230400, 57600, 14400, 3600, 900};
__constant__ int c_coff[NLEV] = {0, 786432, 983040, 1048576, 1064960};
__constant__ int c_ccap[NLEV] = {786432, 196608, 65536, 16384, 8192};
#define CAND_TOTAL 1073152

// k_compact proportional block apportionment
__constant__ int c_cb0[NLEV] = {0, 256, 296, 312, 318};
__constant__ int c_cnb[NLEV] = {256, 40, 16, 6, 2};
#define COMPACT_BLOCKS 320

// -------- scratch (device globals; no allocation allowed) --------
__device__ unsigned long long g_cand[CAND_TOTAL];
__device__ int                g_ccount0[NLEV];
__device__ unsigned           g_hist[NLEV][NBINS];
__device__ int                g_ccount[NLEV];
__device__ unsigned long long g_ckeys[NLEV][CAND_CAP];

__device__ unsigned long long g_keys[5000];
__device__ float  g_score[M_TOTAL];
__device__ int    g_label[M_TOTAL];
__device__ float4 g_box[M_TOTAL];

__device__ float4        g_sbox[M_TOTAL];
__device__ float         g_ssval[M_TOTAL];
__device__ unsigned char g_scls[M_TOTAL];
__device__ unsigned char g_svalid[M_TOTAL];
__device__ unsigned char g_keep[M_TOTAL];

struct PtrSet { const float4* p[NLEV]; };

__device__ __forceinline__ unsigned fmap_pos(float x) {
    return __float_as_uint(x) | 0x80000000u;
}
__device__ __forceinline__ unsigned fmap(float x) {
    unsigned u = __float_as_uint(x);
    return (u & 0x80000000u) ? ~u : (u | 0x80000000u);
}

// ---------------- init scratch ----------------
__global__ void k_init() {
    int t = blockIdx.x * blockDim.x + threadIdx.x;
    if (t < NLEV * NBINS) ((unsigned*)g_hist)[t] = 0;
    if (t < NLEV) { g_ccount0[t] = 0; g_ccount[t] = 0; }
    if (t < 100) g_keys[4900 + t] = 0ULL;
    if (t < M_TOTAL) g_keep[t] = 0;
}

// ------- pass 1: stream 98MB once; positives -> g_cand + histogram --------
__global__ void k_filter(PtrSet cls) {
    int lev = blockIdx.y;
    int n4 = d_LN[lev] * (NCLS / 4);   // divisible by 4 for all levels
    __shared__ unsigned long long stg[STG_CAP];
    __shared__ unsigned shist[NBINS];
    __shared__ int s_cnt, s_base;
    for (int i = threadIdx.x; i < NBINS; i += blockDim.x) shist[i] = 0;
    if (threadIdx.x == 0) s_cnt = 0;
    __syncthreads();

    const float4* __restrict__ p = cls.p[lev];
    unsigned long long* cand = g_cand + c_coff[lev];
    int cap = c_ccap[lev];
    int stride = gridDim.x * blockDim.x * 4;

    for (int i = (blockIdx.x * blockDim.x + threadIdx.x) * 4; i < n4; i += stride) {
        float4 v0 = p[i + 0];
        float4 v1 = p[i + 1];
        float4 v2 = p[i + 2];
        float4 v3 = p[i + 3];
        float vals[16] = {v0.x, v0.y, v0.z, v0.w, v1.x, v1.y, v1.z, v1.w,
                          v2.x, v2.y, v2.z, v2.w, v3.x, v3.y, v3.z, v3.w};
        unsigned base = (unsigned)i * 4u;
        #pragma unroll
        for (int c = 0; c < 16; c++) {
            if (vals[c] > 0.f) {
                unsigned u = fmap_pos(vals[c]);
                atomicAdd(&shist[(u >> 20) - 2048u], 1u);
                unsigned long long key =
                    ((unsigned long long)u << 32) |
                    (unsigned long long)(0xFFFFFFFFu - (base + c));
                int pos = atomicAdd(&s_cnt, 1);
                if (pos < STG_CAP) stg[pos] = key;
                else {
                    int gp = atomicAdd(&g_ccount0[lev], 1);
                    if (gp < cap) cand[gp] = key;
                }
            }
        }
    }
    __syncthreads();
    int cnt = min(s_cnt, STG_CAP);
    if (threadIdx.x == 0) s_base = atomicAdd(&g_ccount0[lev], cnt);
    __syncthreads();
    for (int i = threadIdx.x; i < cnt; i += blockDim.x) {
        int gp = s_base + i;
        if (gp < cap) cand[gp] = stg[i];
    }
    for (int i = threadIdx.x; i < NBINS; i += blockDim.x)
        if (shist[i]) atomicAdd(&g_hist[lev][i], shist[i]);
}

// ------- compact above threshold; per-block warp suffix-scan threshold ----
__global__ void k_compact() {
    int b = blockIdx.x;
    int lev = (b < 256) ? 0 : (b < 296) ? 1 : (b < 312) ? 2 : (b < 318) ? 3 : 4;
    int brel = b - c_cb0[lev];
    int nb   = c_cnb[lev];

    __shared__ unsigned sh[NBINS];
    __shared__ unsigned s_ut;
    int tid = threadIdx.x;
    for (int i = tid; i < NBINS; i += 256) sh[i] = g_hist[lev][i];
    __syncthreads();

    if (tid < 32) {  // warp 0: largest bin b with suffix(b) >= k
        unsigned k = (lev == 4) ? 900u : 1000u;
        unsigned sum = 0;
        #pragma unroll 8
        for (int j = 0; j < 64; j++) sum += sh[tid * 64 + j];
        unsigned suf = sum;
        #pragma unroll
        for (int o = 1; o < 32; o <<= 1) {
            unsigned v = __shfl_down_sync(FULLMASK, suf, o);
            if (tid + o < 32) suf += v;
        }
        unsigned above = suf - sum;   // total in chunks > tid
        if (above < k && above + sum >= k) {
            unsigned acc = above;
            for (int j = 63; j >= 0; j--) {
                acc += sh[tid * 64 + j];
                if (acc >= k) { s_ut = ((unsigned)(tid * 64 + j + 2048)) << 20; break; }
            }
        }
    }
    __syncthreads();
    unsigned ut = s_ut;

    int cc = min(g_ccount0[lev], c_ccap[lev]);
    const unsigned long long* __restrict__ cand = g_cand + c_coff[lev];
    int stride = nb * 256 * 4;
    for (int i = (brel * 256 + tid) * 4; i < cc; i += stride) {
        unsigned long long k0 = cand[i];
        unsigned long long k1 = (i + 1 < cc) ? cand[i + 1] : 0ULL;
        unsigned long long k2 = (i + 2 < cc) ? cand[i + 2] : 0ULL;
        unsigned long long k3 = (i + 3 < cc) ? cand[i + 3] : 0ULL;
        unsigned long long ks[4] = {k0, k1, k2, k3};
        #pragma unroll
        for (int q = 0; q < 4; q++) {
            if ((unsigned)(ks[q] >> 32) >= ut) {
                int pos = atomicAdd(&g_ccount[lev], 1);
                if (pos < CAND_CAP) g_ckeys[lev][pos] = ks[q];
            }
        }
    }
}

// ---------------- bitonic sort (descending) in shared memory --------------
__device__ __forceinline__ void bitonic_desc(unsigned long long* sk, int N) {
    for (int size = 2; size <= N; size <<= 1) {
        for (int stride = size >> 1; stride > 0; stride >>= 1) {
            __syncthreads();
            for (int t = threadIdx.x; t < (N >> 1); t += blockDim.x) {
                int i = ((t & ~(stride - 1)) << 1) | (t & (stride - 1));
                int j = i | stride;
                unsigned long long a = sk[i], b = sk[j];
                bool desc = ((i & size) == 0);
                if ((a < b) == desc) { sk[i] = b; sk[j] = a; }
            }
        }
    }
    __syncthreads();
}

// ------- per level: sort <=4096 candidates, emit top-k + merge keys -------
__global__ void k_lsort(PtrSet boxes) {
    __shared__ unsigned long long sk[CAND_CAP];
    int lev = blockIdx.x;
    int cc = min(g_ccount[lev], CAND_CAP);
    int N = 1024;
    while (N < cc) N <<= 1;
    for (int i = threadIdx.x; i < N; i += blockDim.x)
        sk[i] = (i < cc) ? g_ckeys[lev][i] : 0ULL;
    __syncthreads();
    bitonic_desc(sk, N);

    int k = (lev == 4) ? 900 : 1000;
    int off = lev * 1000;
    const float4* __restrict__ bx = boxes.p[lev];
    for (int r = threadIdx.x; r < k; r += blockDim.x) {
        unsigned long long key = sk[r];
        unsigned u = (unsigned)(key >> 32);
        float logit = __uint_as_float(u & 0x7FFFFFFFu);
        float score = 1.0f / (1.0f + expf(-logit));
        unsigned flat = 0xFFFFFFFFu - (unsigned)(key & 0xFFFFFFFFull);
        float sv = (score > CONF_T) ? score : 0.0f;
        int gi = off + r;
        g_score[gi] = score;
        g_label[gi] = (int)(flat % NCLS);
        g_box[gi] = bx[flat / NCLS];
        g_keys[gi] = ((unsigned long long)fmap(sv) << 32) |
                     (unsigned long long)(0xFFFFFFFFu - (unsigned)gi);
    }
}

// ------- merge-rank: scatter to sorted-position arrays --------------------
__global__ void k_rank() {
    __shared__ unsigned long long keys[5000];
    int tid = threadIdx.x;
    for (int i = tid; i < 5000; i += blockDim.x) keys[i] = g_keys[i];
    __syncthreads();

    int i = blockIdx.x * blockDim.x + tid;
    if (i >= M_TOTAL) return;
    unsigned long long myk = keys[i];
    int myLev = i / 1000;
    int rank = i - myLev * 1000;
    #pragma unroll
    for (int L = 0; L < NLEV; L++) {
        if (L == myLev) continue;
        int base = L * 1000;
        int lo = 0, hi = 1000;
        while (lo < hi) {
            int mid = (lo + hi) >> 1;
            if (keys[base + mid] > myk) lo = mid + 1; else hi = mid;
        }
        rank += lo;
    }
    float sc = g_score[i];
    float sv = (sc > CONF_T) ? sc : 0.0f;
    g_sbox[rank] = g_box[i];
    g_ssval[rank] = sv;
    g_scls[rank] = (unsigned char)g_label[i];
    g_svalid[rank] = (sv > CONF_T) ? 1 : 0;
}

// ------- per-class NMS: one block per class, register+shuffle -------------
__global__ void k_nms() {
    __shared__ unsigned char scls[M_TOTAL];
    __shared__ unsigned char sval[M_TOTAL];
    __shared__ unsigned short wlist[128];
    int c = blockIdx.x;
    int tid = threadIdx.x;

    for (int t = tid; t < M_TOTAL; t += blockDim.x) {
        scls[t] = g_scls[t];
        sval[t] = g_svalid[t];
    }
    __syncthreads();
    if (tid >= 32) return;
    int lane = tid;

    int m = 0;
    for (int base = 0; base < M_TOTAL; base += 32) {
        int t = base + lane;
        bool hit = (t < M_TOTAL) && (scls[t] == (unsigned char)c) && sval[t];
        unsigned bal = __ballot_sync(FULLMASK, hit);
        if (hit) {
            int p = m + __popc(bal & ((1u << lane) - 1u));
            if (p < 128) wlist[p] = (unsigned short)t;
        }
        m += __popc(bal);
    }
    m = min(m, 128);
    __syncwarp();

    int   tq[4];
    float bxl[4], byl[4], bxh[4], byh[4], ar[4];
    int   alv[4];
    #pragma unroll
    for (int q = 0; q < 4; q++) {
        int s = q * 32 + lane;
        if (s < m) {
            int t = wlist[s];
            tq[q] = t;
            float4 b = g_sbox[t];
            bxl[q] = b.x; byl[q] = b.y; bxh[q] = b.z; byh[q] = b.w;
            ar[q] = fmaxf(b.z - b.x, 0.f) * fmaxf(b.w - b.y, 0.f);
            alv[q] = 1;
        } else { tq[q] = -1; alv[q] = 0;
                 bxl[q] = byl[q] = bxh[q] = byh[q] = ar[q] = 0.f; }
    }

    for (int ii = 0; ii < m; ii++) {
        int q = ii >> 5, src = ii & 31;
        float cx1, cy1, cx2, cy2, ca; int cal;
        if (q == 0)      { cx1=bxl[0];cy1=byl[0];cx2=bxh[0];cy2=byh[0];ca=ar[0];cal=alv[0]; }
        else if (q == 1) { cx1=bxl[1];cy1=byl[1];cx2=bxh[1];cy2=byh[1];ca=ar[1];cal=alv[1]; }
        else if (q == 2) { cx1=bxl[2];cy1=byl[2];cx2=bxh[2];cy2=byh[2];ca=ar[2];cal=alv[2]; }
        else             { cx1=bxl[3];cy1=byl[3];cx2=bxh[3];cy2=byh[3];ca=ar[3];cal=alv[3]; }
        cx1 = __shfl_sync(FULLMASK, cx1, src);
        cy1 = __shfl_sync(FULLMASK, cy1, src);
        cx2 = __shfl_sync(FULLMASK, cx2, src);
        cy2 = __shfl_sync(FULLMASK, cy2, src);
        ca  = __shfl_sync(FULLMASK, ca,  src);
        cal = __shfl_sync(FULLMASK, cal, src);
        if (!cal) continue;
        #pragma unroll
        for (int q2 = 0; q2 < 4; q2++) {
            int s = q2 * 32 + lane;
            if (s > ii && alv[q2]) {
                float lx = fmaxf(cx1, bxl[q2]), ly = fmaxf(cy1, byl[q2]);
                float rx = fminf(cx2, bxh[q2]), ry = fminf(cy2, byh[q2]);
                float iw = fmaxf(rx - lx, 0.f), ih = fmaxf(ry - ly, 0.f);
                float inter = iw * ih;
                float iou = inter / (ca + ar[q2] - inter + 1e-9f);
                if (iou > NMS_T) alv[q2] = 0;
            }
        }
    }
    #pragma unroll
    for (int q = 0; q < 4; q++)
        if (tq[q] >= 0 && alv[q]) g_keep[tq[q]] = 1;
}

// ---------------- final output write ----------------
__global__ void k_write(float* __restrict__ out) {
    int t = blockIdx.x * blockDim.x + threadIdx.x;
    if (t >= M_TOTAL) return;
    float kf = g_keep[t] ? 1.0f : 0.0f;
    float4 b = g_sbox[t];
    const float inv = 1.0f / IMG_F;
    out[t * 4 + 0] = fminf(fmaxf(b.x * inv, 0.f), 1.f) * kf;
    out[t * 4 + 1] = fminf(fmaxf(b.y * inv, 0.f), 1.f) * kf;
    out[t * 4 + 2] = fminf(fmaxf(b.z * inv, 0.f), 1.f) * kf;
    out[t * 4 + 3] = fminf(fmaxf(b.w * inv, 0.f), 1.f) * kf;
    out[4 * M_TOTAL + t] = g_ssval[t] * kf;
    out[5 * M_TOTAL + t] = (float)g_scls[t];
    out[6 * M_TOTAL + t] = kf;
}

extern "C" void kernel_launch(void* const* d_in, const int* in_sizes, int n_in,
                              void* d_out, int out_size) {
    (void)in_sizes; (void)n_in; (void)out_size;
    // metadata order is INTERLEAVED: cls0, box0, cls1, box1, ...
    PtrSet cls, box;
    for (int i = 0; i < NLEV; i++) {
        cls.p[i] = (const float4*)d_in[2 * i];
        box.p[i] = (const float4*)d_in[2 * i + 1];
    }
    float* out = (float*)d_out;

    k_init<<<40, 256>>>();                        // 1
    k_filter<<<dim3(512, NLEV), 256>>>(cls);      // 2
    k_compact<<<COMPACT_BLOCKS, 256>>>();         // 3
    k_lsort<<<NLEV, 1024>>>(box);                 // 4 <- profiled slot
    k_rank<<<40, 128>>>();                        // 5
    k_nms<<<NCLS, 128>>>();                       // 6
    k_write<<<(M_TOTAL + 255) / 256, 256>>>(out); // 7
}

// round 10
// speedup vs baseline: 1.6741x; 1.6741x over previous
#include <cuda_runtime.h>
#include <stdint.h>

#define NLEV      5
#define NCLS      80
#define M_TOTAL   4900
#define CAND_CAP  4096
#define NBINS     2048
#define IMG_F     1280.0f
#define CONF_T    0.05f
#define NMS_T     0.6f
#define STG_CAP   2048
#define FULLMASK  0xFFFFFFFFu

__constant__ int d_LN[NLEV]   = {230400, 57600, 14400, 3600, 900};
__constant__ int c_coff[NLEV] = {0, 786432, 983040, 1048576, 1064960};
__constant__ int c_ccap[NLEV] = {786432, 196608, 65536, 16384, 8192};
#define CAND_TOTAL 1073152

// k_compact proportional block apportionment
__constant__ int c_cb0[NLEV] = {0, 256, 296, 312, 318};
__constant__ int c_cnb[NLEV] = {256, 40, 16, 6, 2};
#define COMPACT_BLOCKS 320

// -------- scratch (device globals; no allocation allowed) --------
__device__ unsigned long long g_cand[CAND_TOTAL];
__device__ int                g_ccount0[NLEV];
__device__ unsigned           g_hist[NLEV][NBINS];
__device__ int                g_ccount[NLEV];
__device__ unsigned long long g_ckeys[NLEV][CAND_CAP];

__device__ unsigned long long g_keys[5000];
__device__ float  g_score[M_TOTAL];
__device__ int    g_label[M_TOTAL];
__device__ float4 g_box[M_TOTAL];

__device__ float4        g_sbox[M_TOTAL];
__device__ float         g_ssval[M_TOTAL];
__device__ unsigned char g_scls[M_TOTAL];
__device__ unsigned char g_svalid[M_TOTAL];
__device__ unsigned char g_keep[M_TOTAL];

struct PtrSet { const float4* p[NLEV]; };

__device__ __forceinline__ unsigned fmap_pos(float x) {
    return __float_as_uint(x) | 0x80000000u;
}
__device__ __forceinline__ unsigned fmap(float x) {
    unsigned u = __float_as_uint(x);
    return (u & 0x80000000u) ? ~u : (u | 0x80000000u);
}

// ---------------- init scratch ----------------
__global__ void k_init() {
    int t = blockIdx.x * blockDim.x + threadIdx.x;
    if (t < NLEV * NBINS) ((unsigned*)g_hist)[t] = 0;
    if (t < NLEV) { g_ccount0[t] = 0; g_ccount[t] = 0; }
    if (t < 100) g_keys[4900 + t] = 0ULL;
    if (t < M_TOTAL) g_keep[t] = 0;
}

// ------- pass 1 (R7-measured shape): positives -> g_cand + histogram ------
__global__ void k_filter(PtrSet cls) {
    int lev = blockIdx.y;
    int n4 = d_LN[lev] * (NCLS / 4);
    __shared__ unsigned shist[NBINS];
    __shared__ unsigned long long stg[STG_CAP];
    __shared__ int s_cnt, s_base;
    for (int i = threadIdx.x; i < NBINS; i += blockDim.x) shist[i] = 0;
    if (threadIdx.x == 0) s_cnt = 0;
    __syncthreads();

    const float4* __restrict__ p = cls.p[lev];
    unsigned long long* cand = g_cand + c_coff[lev];
    int cap = c_ccap[lev];
    int stride = gridDim.x * blockDim.x * 2;

    for (int i = (blockIdx.x * blockDim.x + threadIdx.x) * 2; i < n4; i += stride) {
        float4 v0 = p[i];
        float4 v1 = (i + 1 < n4) ? p[i + 1] : make_float4(-1.f, -1.f, -1.f, -1.f);
        float vals[8] = {v0.x, v0.y, v0.z, v0.w, v1.x, v1.y, v1.z, v1.w};
        unsigned base = (unsigned)i * 4u;
        #pragma unroll
        for (int c = 0; c < 8; c++) {
            if (vals[c] > 0.f) {
                unsigned u = fmap_pos(vals[c]);
                atomicAdd(&shist[(u >> 20) - 2048u], 1u);
                unsigned long long key =
                    ((unsigned long long)u << 32) |
                    (unsigned long long)(0xFFFFFFFFu - (base + c));
                int pos = atomicAdd(&s_cnt, 1);
                if (pos < STG_CAP) stg[pos] = key;
                else {
                    int gp = atomicAdd(&g_ccount0[lev], 1);
                    if (gp < cap) cand[gp] = key;
                }
            }
        }
    }
    __syncthreads();
    int cnt = min(s_cnt, STG_CAP);
    if (threadIdx.x == 0) s_base = atomicAdd(&g_ccount0[lev], cnt);
    __syncthreads();
    for (int i = threadIdx.x; i < cnt; i += blockDim.x) {
        int gp = s_base + i;
        if (gp < cap) cand[gp] = stg[i];
    }
    for (int i = threadIdx.x; i < NBINS; i += blockDim.x)
        if (shist[i]) atomicAdd(&g_hist[lev][i], shist[i]);
}

// ------- compact above threshold; per-block warp suffix-scan threshold ----
__global__ void k_compact() {
    int b = blockIdx.x;
    int lev = (b < 256) ? 0 : (b < 296) ? 1 : (b < 312) ? 2 : (b < 318) ? 3 : 4;
    int brel = b - c_cb0[lev];
    int nb   = c_cnb[lev];

    __shared__ unsigned sh[NBINS];
    __shared__ unsigned s_ut;
    int tid = threadIdx.x;
    for (int i = tid; i < NBINS; i += 256) sh[i] = g_hist[lev][i];
    __syncthreads();

    if (tid < 32) {  // warp 0: largest bin b with suffix(b) >= k
        unsigned k = (lev == 4) ? 900u : 1000u;
        unsigned sum = 0;
        #pragma unroll 8
        for (int j = 0; j < 64; j++) sum += sh[tid * 64 + j];
        unsigned suf = sum;
        #pragma unroll
        for (int o = 1; o < 32; o <<= 1) {
            unsigned v = __shfl_down_sync(FULLMASK, suf, o);
            if (tid + o < 32) suf += v;
        }
        unsigned above = suf - sum;   // total in chunks > tid
        if (above < k && above + sum >= k) {
            unsigned acc = above;
            for (int j = 63; j >= 0; j--) {
                acc += sh[tid * 64 + j];
                if (acc >= k) { s_ut = ((unsigned)(tid * 64 + j + 2048)) << 20; break; }
            }
        }
    }
    __syncthreads();
    unsigned ut = s_ut;

    int cc = min(g_ccount0[lev], c_ccap[lev]);
    const unsigned long long* __restrict__ cand = g_cand + c_coff[lev];
    int stride = nb * 256 * 4;
    for (int i = (brel * 256 + tid) * 4; i < cc; i += stride) {
        unsigned long long k0 = cand[i];
        unsigned long long k1 = (i + 1 < cc) ? cand[i + 1] : 0ULL;
        unsigned long long k2 = (i + 2 < cc) ? cand[i + 2] : 0ULL;
        unsigned long long k3 = (i + 3 < cc) ? cand[i + 3] : 0ULL;
        unsigned long long ks[4] = {k0, k1, k2, k3};
        #pragma unroll
        for (int q = 0; q < 4; q++) {
            if ((unsigned)(ks[q] >> 32) >= ut) {
                int pos = atomicAdd(&g_ccount[lev], 1);
                if (pos < CAND_CAP) g_ckeys[lev][pos] = ks[q];
            }
        }
    }
}

// ------- per level: rank-by-count among <=4096 candidates, emit top-k -----
__global__ void k_rankl(PtrSet boxes) {
    __shared__ unsigned long long sk[CAND_CAP];   // 32 KB
    int b = blockIdx.x;
    int lev = b >> 3;           // 8 blocks per level
    int brel = b & 7;
    int cc = min(g_ccount[lev], CAND_CAP);
    for (int i = threadIdx.x; i < cc; i += 256) sk[i] = g_ckeys[lev][i];
    __syncthreads();

    int k = (lev == 4) ? 900 : 1000;
    int off = lev * 1000;
    const float4* __restrict__ bx = boxes.p[lev];

    for (int i = brel * 256 + threadIdx.x; i < cc; i += 8 * 256) {
        unsigned long long myk = sk[i];
        int rank = 0;
        int j = 0;
        for (; j + 4 <= cc; j += 4) {
            rank += (sk[j]     > myk);
            rank += (sk[j + 1] > myk);
            rank += (sk[j + 2] > myk);
            rank += (sk[j + 3] > myk);
        }
        for (; j < cc; j++) rank += (sk[j] > myk);
        if (rank < k) {
            unsigned u = (unsigned)(myk >> 32);
            float logit = __uint_as_float(u & 0x7FFFFFFFu);
            float score = 1.0f / (1.0f + expf(-logit));
            unsigned flat = 0xFFFFFFFFu - (unsigned)(myk & 0xFFFFFFFFull);
            float sv = (score > CONF_T) ? score : 0.0f;
            int gi = off + rank;
            g_score[gi] = score;
            g_label[gi] = (int)(flat % NCLS);
            g_box[gi] = bx[flat / NCLS];
            g_keys[gi] = ((unsigned long long)fmap(sv) << 32) |
                         (unsigned long long)(0xFFFFFFFFu - (unsigned)gi);
        }
    }
}

// ------- merge-rank: scatter to sorted-position arrays --------------------
__global__ void k_rank() {
    __shared__ unsigned long long keys[5000];
    int tid = threadIdx.x;
    for (int i = tid; i < 5000; i += blockDim.x) keys[i] = g_keys[i];
    __syncthreads();

    int i = blockIdx.x * blockDim.x + tid;
    if (i >= M_TOTAL) return;
    unsigned long long myk = keys[i];
    int myLev = i / 1000;
    int rank = i - myLev * 1000;
    #pragma unroll
    for (int L = 0; L < NLEV; L++) {
        if (L == myLev) continue;
        int base = L * 1000;
        int lo = 0, hi = 1000;
        while (lo < hi) {
            int mid = (lo + hi) >> 1;
            if (keys[base + mid] > myk) lo = mid + 1; else hi = mid;
        }
        rank += lo;
    }
    float sc = g_score[i];
    float sv = (sc > CONF_T) ? sc : 0.0f;
    g_sbox[rank] = g_box[i];
    g_ssval[rank] = sv;
    g_scls[rank] = (unsigned char)g_label[i];
    g_svalid[rank] = (sv > CONF_T) ? 1 : 0;
}

// ------- per-class NMS: one block per class, register+shuffle -------------
__global__ void k_nms() {
    __shared__ unsigned char scls[M_TOTAL];
    __shared__ unsigned char sval[M_TOTAL];
    __shared__ unsigned short wlist[128];
    int c = blockIdx.x;
    int tid = threadIdx.x;

    for (int t = tid; t < M_TOTAL; t += blockDim.x) {
        scls[t] = g_scls[t];
        sval[t] = g_svalid[t];
    }
    __syncthreads();
    if (tid >= 32) return;
    int lane = tid;

    int m = 0;
    for (int base = 0; base < M_TOTAL; base += 32) {
        int t = base + lane;
        bool hit = (t < M_TOTAL) && (scls[t] == (unsigned char)c) && sval[t];
        unsigned bal = __ballot_sync(FULLMASK, hit);
        if (hit) {
            int p = m + __popc(bal & ((1u << lane) - 1u));
            if (p < 128) wlist[p] = (unsigned short)t;
        }
        m += __popc(bal);
    }
    m = min(m, 128);
    __syncwarp();

    int   tq[4];
    float bxl[4], byl[4], bxh[4], byh[4], ar[4];
    int   alv[4];
    #pragma unroll
    for (int q = 0; q < 4; q++) {
        int s = q * 32 + lane;
        if (s < m) {
            int t = wlist[s];
            tq[q] = t;
            float4 b = g_sbox[t];
            bxl[q] = b.x; byl[q] = b.y; bxh[q] = b.z; byh[q] = b.w;
            ar[q] = fmaxf(b.z - b.x, 0.f) * fmaxf(b.w - b.y, 0.f);
            alv[q] = 1;
        } else { tq[q] = -1; alv[q] = 0;
                 bxl[q] = byl[q] = bxh[q] = byh[q] = ar[q] = 0.f; }
    }

    for (int ii = 0; ii < m; ii++) {
        int q = ii >> 5, src = ii & 31;
        float cx1, cy1, cx2, cy2, ca; int cal;
        if (q == 0)      { cx1=bxl[0];cy1=byl[0];cx2=bxh[0];cy2=byh[0];ca=ar[0];cal=alv[0]; }
        else if (q == 1) { cx1=bxl[1];cy1=byl[1];cx2=bxh[1];cy2=byh[1];ca=ar[1];cal=alv[1]; }
        else if (q == 2) { cx1=bxl[2];cy1=byl[2];cx2=bxh[2];cy2=byh[2];ca=ar[2];cal=alv[2]; }
        else             { cx1=bxl[3];cy1=byl[3];cx2=bxh[3];cy2=byh[3];ca=ar[3];cal=alv[3]; }
        cx1 = __shfl_sync(FULLMASK, cx1, src);
        cy1 = __shfl_sync(FULLMASK, cy1, src);
        cx2 = __shfl_sync(FULLMASK, cx2, src);
        cy2 = __shfl_sync(FULLMASK, cy2, src);
        ca  = __shfl_sync(FULLMASK, ca,  src);
        cal = __shfl_sync(FULLMASK, cal, src);
        if (!cal) continue;
        #pragma unroll
        for (int q2 = 0; q2 < 4; q2++) {
            int s = q2 * 32 + lane;
            if (s > ii && alv[q2]) {
                float lx = fmaxf(cx1, bxl[q2]), ly = fmaxf(cy1, byl[q2]);
                float rx = fminf(cx2, bxh[q2]), ry = fminf(cy2, byh[q2]);
                float iw = fmaxf(rx - lx, 0.f), ih = fmaxf(ry - ly, 0.f);
                float inter = iw * ih;
                float iou = inter / (ca + ar[q2] - inter + 1e-9f);
                if (iou > NMS_T) alv[q2] = 0;
            }
        }
    }
    #pragma unroll
    for (int q = 0; q < 4; q++)
        if (tq[q] >= 0 && alv[q]) g_keep[tq[q]] = 1;
}

// ---------------- final output write ----------------
__global__ void k_write(float* __restrict__ out) {
    int t = blockIdx.x * blockDim.x + threadIdx.x;
    if (t >= M_TOTAL) return;
    float kf = g_keep[t] ? 1.0f : 0.0f;
    float4 b = g_sbox[t];
    const float inv = 1.0f / IMG_F;
    out[t * 4 + 0] = fminf(fmaxf(b.x * inv, 0.f), 1.f) * kf;
    out[t * 4 + 1] = fminf(fmaxf(b.y * inv, 0.f), 1.f) * kf;
    out[t * 4 + 2] = fminf(fmaxf(b.z * inv, 0.f), 1.f) * kf;
    out[t * 4 + 3] = fminf(fmaxf(b.w * inv, 0.f), 1.f) * kf;
    out[4 * M_TOTAL + t] = g_ssval[t] * kf;
    out[5 * M_TOTAL + t] = (float)g_scls[t];
    out[6 * M_TOTAL + t] = kf;
}

extern "C" void kernel_launch(void* const* d_in, const int* in_sizes, int n_in,
                              void* d_out, int out_size) {
    (void)in_sizes; (void)n_in; (void)out_size;
    // metadata order is INTERLEAVED: cls0, box0, cls1, box1, ...
    PtrSet cls, box;
    for (int i = 0; i < NLEV; i++) {
        cls.p[i] = (const float4*)d_in[2 * i];
        box.p[i] = (const float4*)d_in[2 * i + 1];
    }
    float* out = (float*)d_out;

    k_init<<<40, 256>>>();                        // 1
    k_filter<<<dim3(512, NLEV), 256>>>(cls);      // 2
    k_compact<<<COMPACT_BLOCKS, 256>>>();         // 3
    k_rankl<<<40, 256>>>(box);                    // 4 <- profiled slot
    k_rank<<<40, 128>>>();                        // 5
    k_nms<<<NCLS, 128>>>();                       // 6
    k_write<<<(M_TOTAL + 255) / 256, 256>>>(out); // 7
}